// round 2
// baseline (speedup 1.0000x reference)
#include <cuda_runtime.h>
#include <cuda_bf16.h>

#define DD 1024
#define HH 1024
#define BB 8192

__device__ __align__(16) float g_mTab[DD * HH];  // m[d][h] = exp(-W[h][d])
__device__ unsigned            g_xb[BB * 32];    // packed x bits [b][d/32]
__device__ __align__(16) float g_rinit[HH];      // sigmoid(c[h])

typedef unsigned long long u64;

__device__ __forceinline__ u64 fma2_(u64 a, u64 b, u64 c) {
    u64 d; asm("fma.rn.f32x2 %0, %1, %2, %3;" : "=l"(d) : "l"(a), "l"(b), "l"(c)); return d;
}
__device__ __forceinline__ u64 mul2_(u64 a, u64 b) {
    u64 d; asm("mul.rn.f32x2 %0, %1, %2;" : "=l"(d) : "l"(a), "l"(b)); return d;
}
__device__ __forceinline__ u64 add2_(u64 a, u64 b) {
    u64 d; asm("add.rn.f32x2 %0, %1, %2;" : "=l"(d) : "l"(a), "l"(b)); return d;
}
__device__ __forceinline__ float frcp_(float x) {
    float r; asm("rcp.approx.f32 %0, %1;" : "=f"(r) : "f"(x)); return r;
}
__device__ __forceinline__ float fex2_(float x) {
    float r; asm("ex2.approx.f32 %0, %1;" : "=f"(r) : "f"(x)); return r;
}
__device__ __forceinline__ u64 pack2_(float lo, float hi) {
    u64 u; asm("mov.b64 %0, {%1, %2};" : "=l"(u) : "f"(lo), "f"(hi)); return u;
}
__device__ __forceinline__ void unpack2_(u64 u, float& a, float& b) {
    asm("mov.b64 {%0, %1}, %2;" : "=f"(a), "=f"(b) : "l"(u));
}
__device__ __forceinline__ float sigm_(float t) {
    return frcp_(1.0f + fex2_(-1.4426950408889634f * t));
}
__device__ __forceinline__ void cp16(void* sdst, const void* gsrc) {
    unsigned s = (unsigned)__cvta_generic_to_shared(sdst);
    asm volatile("cp.async.cg.shared.global [%0], [%1], 16;" :: "r"(s), "l"(gsrc));
}
__device__ __forceinline__ void cp_commit() { asm volatile("cp.async.commit_group;"); }
__device__ __forceinline__ void cp_wait1()  { asm volatile("cp.async.wait_group 1;"); }

// -------- precompute --------
__global__ void prep_m(const float* __restrict__ W) {
    int i = blockIdx.x * 256 + threadIdx.x;   // over H*D, W row-major [H][D]
    int h = i >> 10, d = i & 1023;
    g_mTab[d * HH + h] = __expf(-W[i]);
}
__global__ void prep_xb(const float* __restrict__ x) {
    int gtid = blockIdx.x * 256 + threadIdx.x;
    int warp = gtid >> 5, lane = gtid & 31;
    int b = warp >> 5, ch = warp & 31;
    float v = x[b * DD + ch * 32 + lane];
    unsigned m = __ballot_sync(0xffffffffu, v != 0.0f);
    if (lane == 0) g_xb[b * 32 + ch] = m;
}
__global__ void prep_r(const float* __restrict__ c) {
    int h = blockIdx.x * 256 + threadIdx.x;
    if (h < HH) g_rinit[h] = 1.0f / (1.0f + __expf(-c[h]));
}

// -------- main: warp = 4 batch rows, lane owns 32 h-values --------
__global__ void __launch_bounds__(128, 2)
nade_main(const float* __restrict__ V, const float* __restrict__ bvec,
          float* __restrict__ out) {
    __shared__ __align__(16) float sV[4][HH];
    __shared__ __align__(16) float sM[4][HH];
    __shared__ float sB[DD];

    const int tid = threadIdx.x, lane = tid & 31, wid = tid >> 5;
    const int b0 = blockIdx.x * 16 + wid * 4;

    #pragma unroll
    for (int i = tid; i < DD; i += 128) sB[i] = bvec[i];

    u64 r2[4][16];
    #pragma unroll
    for (int q = 0; q < 8; ++q) {
        const int hb = (lane + 32 * q) * 4;
        u64 plo = pack2_(g_rinit[hb], g_rinit[hb + 1]);
        u64 phi = pack2_(g_rinit[hb + 2], g_rinit[hb + 3]);
        #pragma unroll
        for (int rr = 0; rr < 4; ++rr) { r2[rr][2*q] = plo; r2[rr][2*q+1] = phi; }
    }

    // prefetch rows 0,1
    #pragma unroll
    for (int pr = 0; pr < 2; ++pr) {
        const float* vs = V + pr * HH;
        const float* ms = g_mTab + pr * HH;
        cp16(&sV[pr][tid*4], vs + tid*4);  cp16(&sV[pr][512 + tid*4], vs + 512 + tid*4);
        cp16(&sM[pr][tid*4], ms + tid*4);  cp16(&sM[pr][512 + tid*4], ms + 512 + tid*4);
        cp_commit();
    }

    const u64 ONE2 = 0x3f8000003f800000ULL;
    const u64 SGN2 = 0x8000000080000000ULL;
    unsigned bits[4];
    float pb[4];

    #pragma unroll 1
    for (int d4 = 0; d4 < DD / 4; ++d4) {
        if ((d4 & 7) == 0) {
            const int w = d4 >> 3;
            #pragma unroll
            for (int rr = 0; rr < 4; ++rr) bits[rr] = g_xb[(b0 + rr) * 32 + w];
        }

        #pragma unroll
        for (int k = 0; k < 4; ++k) {
            const int d = d4 * 4 + k;
            cp_wait1();
            __syncthreads();
            if (d + 2 < DD) {
                const int slot = (k + 2) & 3;
                const float* vs = V + (d + 2) * HH;
                const float* ms = g_mTab + (d + 2) * HH;
                cp16(&sV[slot][tid*4], vs + tid*4);  cp16(&sV[slot][512 + tid*4], vs + 512 + tid*4);
                cp16(&sM[slot][tid*4], ms + tid*4);  cp16(&sM[slot][512 + tid*4], ms + 512 + tid*4);
            }
            cp_commit();

            // dot: acc[rr] += r[rr] . V[d]
            u64 acc0 = 0ULL, acc1 = 0ULL, acc2 = 0ULL, acc3 = 0ULL;
            #pragma unroll
            for (int q = 0; q < 8; ++q) {
                const ulonglong2 v = *reinterpret_cast<const ulonglong2*>(&sV[k][(lane + 32*q)*4]);
                acc0 = fma2_(r2[0][2*q], v.x, acc0); acc0 = fma2_(r2[0][2*q+1], v.y, acc0);
                acc1 = fma2_(r2[1][2*q], v.x, acc1); acc1 = fma2_(r2[1][2*q+1], v.y, acc1);
                acc2 = fma2_(r2[2][2*q], v.x, acc2); acc2 = fma2_(r2[2][2*q+1], v.y, acc2);
                acc3 = fma2_(r2[3][2*q], v.x, acc3); acc3 = fma2_(r2[3][2*q+1], v.y, acc3);
            }
            float s0, s1, s2, s3;
            { float a, b; unpack2_(acc0, a, b); s0 = a + b; }
            { float a, b; unpack2_(acc1, a, b); s1 = a + b; }
            { float a, b; unpack2_(acc2, a, b); s2 = a + b; }
            { float a, b; unpack2_(acc3, a, b); s3 = a + b; }
            #pragma unroll
            for (int off = 16; off; off >>= 1) {
                s0 += __shfl_xor_sync(0xffffffffu, s0, off);
                s1 += __shfl_xor_sync(0xffffffffu, s1, off);
                s2 += __shfl_xor_sync(0xffffffffu, s2, off);
                s3 += __shfl_xor_sync(0xffffffffu, s3, off);
            }
            float tsel = s0;
            if (lane == 1) tsel = s1;
            if (lane == 2) tsel = s2;
            if (lane == 3) tsel = s3;
            pb[k] = sigm_(sB[d] + tsel);   // only lanes 0..3 meaningful

            // state update for rr's with x==1 (warp-uniform branch)
            const unsigned bit = 1u << (d & 31);
            #pragma unroll
            for (int rr = 0; rr < 4; ++rr) {
                if (bits[rr] & bit) {
                    #pragma unroll
                    for (int q = 0; q < 8; ++q) {
                        const ulonglong2 m = *reinterpret_cast<const ulonglong2*>(&sM[k][(lane + 32*q)*4]);
                        {
                            u64 u2 = add2_(ONE2, m.x ^ SGN2);                 // 1 - m
                            u64 den = fma2_(r2[rr][2*q], u2, m.x);            // m + r(1-m)
                            float dl, dh; unpack2_(den, dl, dh);
                            r2[rr][2*q] = mul2_(r2[rr][2*q], pack2_(frcp_(dl), frcp_(dh)));
                        }
                        {
                            u64 u2 = add2_(ONE2, m.y ^ SGN2);
                            u64 den = fma2_(r2[rr][2*q+1], u2, m.y);
                            float dl, dh; unpack2_(den, dl, dh);
                            r2[rr][2*q+1] = mul2_(r2[rr][2*q+1], pack2_(frcp_(dl), frcp_(dh)));
                        }
                    }
                }
            }
        }

        if (lane < 4) {
            float4 o = make_float4(pb[0], pb[1], pb[2], pb[3]);
            *reinterpret_cast<float4*>(&out[(unsigned)(b0 + lane) * DD + d4 * 4]) = o;
        }
    }
}

extern "C" void kernel_launch(void* const* d_in, const int* in_sizes, int n_in,
                              void* d_out, int out_size) {
    const float* x = (const float*)d_in[0];   // (B, D)
    const float* V = (const float*)d_in[1];   // (D, H)
    const float* b = (const float*)d_in[2];   // (D,)
    const float* W = (const float*)d_in[3];   // (H, D)
    const float* c = (const float*)d_in[4];   // (H,)
    float* out = (float*)d_out;               // (B, D)

    prep_m <<<(HH * DD) / 256, 256>>>(W);
    prep_xb<<<(BB * 32 * 32) / 256, 256>>>(x);
    prep_r <<<HH / 256, 256>>>(c);
    nade_main<<<BB / 16, 128>>>(V, b, out);
}

// round 3
// speedup vs baseline: 1.1797x; 1.1797x over previous
#include <cuda_runtime.h>
#include <cuda_bf16.h>

#define DD 1024
#define HH 1024
#define BB 8192

__device__ __align__(16) float g_mTab[DD * HH];  // m[d][h] = exp(-W[h][d])
__device__ unsigned            g_xb[BB * 32];    // packed x bits [b][d/32]
__device__ __align__(16) float g_rinit[HH];      // sigmoid(c[h])
__device__ __align__(16) float g_sinit[HH];      // exp(-c[h])

typedef unsigned long long u64;

__device__ __forceinline__ u64 fma2_(u64 a, u64 b, u64 c) {
    u64 d; asm("fma.rn.f32x2 %0, %1, %2, %3;" : "=l"(d) : "l"(a), "l"(b), "l"(c)); return d;
}
__device__ __forceinline__ u64 mul2_(u64 a, u64 b) {
    u64 d; asm("mul.rn.f32x2 %0, %1, %2;" : "=l"(d) : "l"(a), "l"(b)); return d;
}
__device__ __forceinline__ u64 add2_(u64 a, u64 b) {
    u64 d; asm("add.rn.f32x2 %0, %1, %2;" : "=l"(d) : "l"(a), "l"(b)); return d;
}
__device__ __forceinline__ float frcp_(float x) {
    float r; asm("rcp.approx.f32 %0, %1;" : "=f"(r) : "f"(x)); return r;
}
__device__ __forceinline__ float fex2_(float x) {
    float r; asm("ex2.approx.f32 %0, %1;" : "=f"(r) : "f"(x)); return r;
}
__device__ __forceinline__ u64 pack2_(float lo, float hi) {
    u64 u; asm("mov.b64 %0, {%1, %2};" : "=l"(u) : "f"(lo), "f"(hi)); return u;
}
__device__ __forceinline__ void unpack2_(u64 u, float& a, float& b) {
    asm("mov.b64 {%0, %1}, %2;" : "=f"(a), "=f"(b) : "l"(u));
}
__device__ __forceinline__ float sigm_(float t) {
    return frcp_(1.0f + fex2_(-1.4426950408889634f * t));
}
__device__ __forceinline__ void cp16(void* sdst, const void* gsrc) {
    unsigned s = (unsigned)__cvta_generic_to_shared(sdst);
    asm volatile("cp.async.cg.shared.global [%0], [%1], 16;" :: "r"(s), "l"(gsrc));
}
__device__ __forceinline__ void cp_commit() { asm volatile("cp.async.commit_group;"); }
__device__ __forceinline__ void cp_wait1()  { asm volatile("cp.async.wait_group 1;"); }

// -------- precompute --------
__global__ void prep_m(const float* __restrict__ W) {
    int i = blockIdx.x * 256 + threadIdx.x;   // over H*D, W row-major [H][D]
    int h = i >> 10, d = i & 1023;
    g_mTab[d * HH + h] = __expf(-W[i]);
}
__global__ void prep_xb(const float* __restrict__ x) {
    int gtid = blockIdx.x * 256 + threadIdx.x;
    int warp = gtid >> 5, lane = gtid & 31;
    int b = warp >> 5, ch = warp & 31;
    float v = x[b * DD + ch * 32 + lane];
    unsigned m = __ballot_sync(0xffffffffu, v != 0.0f);
    if (lane == 0) g_xb[b * 32 + ch] = m;
}
__global__ void prep_r(const float* __restrict__ c) {
    int h = blockIdx.x * 256 + threadIdx.x;
    if (h < HH) {
        float cv = c[h];
        g_rinit[h] = 1.0f / (1.0f + __expf(-cv));
        g_sinit[h] = __expf(-cv);
    }
}

// -------- main: warp = 1 batch row, lane owns 32 h-values --------
// State per lane: s = exp(-a) (16 f32x2 pairs) and r = sigmoid(a) (16 pairs).
// Update on x==1: s *= m;  r = rcp(1 + s).
__global__ void __launch_bounds__(256, 2)
nade_main(const float* __restrict__ V, const float* __restrict__ bvec,
          float* __restrict__ out) {
    __shared__ __align__(16) float sV[4][HH];   // 16KB ring of V rows
    __shared__ __align__(16) float sM[4][HH];   // 16KB ring of m rows
    __shared__ float sB[DD];                    // 4KB bias

    const int tid = threadIdx.x, lane = tid & 31, wid = tid >> 5;
    const int b = blockIdx.x * 8 + wid;         // this warp's batch row

    #pragma unroll
    for (int i = tid; i < DD; i += 256) sB[i] = bvec[i];

    u64 r2[16], s2[16];
    #pragma unroll
    for (int q = 0; q < 8; ++q) {
        const int hb = (lane + 32 * q) * 4;
        float4 rv = *reinterpret_cast<const float4*>(&g_rinit[hb]);
        float4 sv = *reinterpret_cast<const float4*>(&g_sinit[hb]);
        r2[2*q]   = pack2_(rv.x, rv.y);  r2[2*q+1] = pack2_(rv.z, rv.w);
        s2[2*q]   = pack2_(sv.x, sv.y);  s2[2*q+1] = pack2_(sv.z, sv.w);
    }

    // prefetch rows 0,1 (one 16B chunk of V and of m per thread per row)
    #pragma unroll
    for (int pr = 0; pr < 2; ++pr) {
        cp16(&sV[pr][tid * 4], V + pr * HH + tid * 4);
        cp16(&sM[pr][tid * 4], g_mTab + pr * HH + tid * 4);
        cp_commit();
    }

    const u64 ONE2 = 0x3f8000003f800000ULL;
    unsigned bits = 0;
    float pb0, pb1, pb2, pb3;

    #pragma unroll 1
    for (int d4 = 0; d4 < DD / 4; ++d4) {
        if ((d4 & 7) == 0) bits = g_xb[b * 32 + (d4 >> 3)];

        #pragma unroll
        for (int k = 0; k < 4; ++k) {
            const int d = d4 * 4 + k;
            cp_wait1();
            __syncthreads();
            if (d + 2 < DD) {
                const int slot = (k + 2) & 3;
                cp16(&sV[slot][tid * 4], V + (d + 2) * HH + tid * 4);
                cp16(&sM[slot][tid * 4], g_mTab + (d + 2) * HH + tid * 4);
            }
            cp_commit();

            // dot: sum_h r[h] * V[d][h]
            u64 acc0 = 0ULL, acc1 = 0ULL;
            #pragma unroll
            for (int q = 0; q < 8; ++q) {
                const ulonglong2 v = *reinterpret_cast<const ulonglong2*>(&sV[k][(lane + 32*q) * 4]);
                acc0 = fma2_(r2[2*q],   v.x, acc0);
                acc1 = fma2_(r2[2*q+1], v.y, acc1);
            }
            acc0 = add2_(acc0, acc1);
            float sa, sb_; unpack2_(acc0, sa, sb_);
            float s = sa + sb_;
            #pragma unroll
            for (int off = 16; off; off >>= 1)
                s += __shfl_xor_sync(0xffffffffu, s, off);
            const float p = sigm_(sB[d] + s);
            if (k == 0) pb0 = p; else if (k == 1) pb1 = p;
            else if (k == 2) pb2 = p; else pb3 = p;

            // state update (warp-uniform branch, prob 1/2)
            if (bits & (1u << (d & 31))) {
                #pragma unroll
                for (int q = 0; q < 8; ++q) {
                    const ulonglong2 m = *reinterpret_cast<const ulonglong2*>(&sM[k][(lane + 32*q) * 4]);
                    s2[2*q]   = mul2_(s2[2*q],   m.x);
                    s2[2*q+1] = mul2_(s2[2*q+1], m.y);
                    u64 den0 = add2_(ONE2, s2[2*q]);
                    u64 den1 = add2_(ONE2, s2[2*q+1]);
                    float d0, d1, d2, d3;
                    unpack2_(den0, d0, d1);
                    unpack2_(den1, d2, d3);
                    r2[2*q]   = pack2_(frcp_(d0), frcp_(d1));
                    r2[2*q+1] = pack2_(frcp_(d2), frcp_(d3));
                }
            }
        }

        if (lane == 0) {
            float4 o = make_float4(pb0, pb1, pb2, pb3);
            *reinterpret_cast<float4*>(&out[(unsigned)b * DD + d4 * 4]) = o;
        }
    }
}

extern "C" void kernel_launch(void* const* d_in, const int* in_sizes, int n_in,
                              void* d_out, int out_size) {
    const float* x = (const float*)d_in[0];   // (B, D)
    const float* V = (const float*)d_in[1];   // (D, H)
    const float* b = (const float*)d_in[2];   // (D,)
    const float* W = (const float*)d_in[3];   // (H, D)
    const float* c = (const float*)d_in[4];   // (H,)
    float* out = (float*)d_out;               // (B, D)

    prep_m <<<(HH * DD) / 256, 256>>>(W);
    prep_xb<<<(BB * 32 * 32) / 256, 256>>>(x);
    prep_r <<<HH / 256, 256>>>(c);
    nade_main<<<BB / 8, 256>>>(V, b, out);
}

// round 5
// speedup vs baseline: 1.5123x; 1.2820x over previous
#include <cuda_runtime.h>
#include <cuda_bf16.h>

#define DD 1024
#define HH 1024
#define BB 8192

__device__ __align__(16) float g_mTab[DD * HH];  // m[d][h] = exp(-W[h][d])
__device__ unsigned            g_xb[BB * 32];    // packed x bits [b][d/32]
__device__ __align__(16) float g_rinit[HH];      // sigmoid(c[h])
__device__ __align__(16) float g_sinit[HH];      // exp(-c[h])

typedef unsigned long long u64;

__device__ __forceinline__ u64 fma2_(u64 a, u64 b, u64 c) {
    u64 d; asm("fma.rn.f32x2 %0, %1, %2, %3;" : "=l"(d) : "l"(a), "l"(b), "l"(c)); return d;
}
__device__ __forceinline__ u64 mul2_(u64 a, u64 b) {
    u64 d; asm("mul.rn.f32x2 %0, %1, %2;" : "=l"(d) : "l"(a), "l"(b)); return d;
}
__device__ __forceinline__ u64 add2_(u64 a, u64 b) {
    u64 d; asm("add.rn.f32x2 %0, %1, %2;" : "=l"(d) : "l"(a), "l"(b)); return d;
}
__device__ __forceinline__ float frcp_(float x) {
    float r; asm("rcp.approx.f32 %0, %1;" : "=f"(r) : "f"(x)); return r;
}
__device__ __forceinline__ float fex2_(float x) {
    float r; asm("ex2.approx.f32 %0, %1;" : "=f"(r) : "f"(x)); return r;
}
__device__ __forceinline__ u64 pack2_(float lo, float hi) {
    u64 u; asm("mov.b64 %0, {%1, %2};" : "=l"(u) : "f"(lo), "f"(hi)); return u;
}
__device__ __forceinline__ void unpack2_(u64 u, float& a, float& b) {
    asm("mov.b64 {%0, %1}, %2;" : "=f"(a), "=f"(b) : "l"(u));
}
__device__ __forceinline__ float sigm_(float t) {
    return frcp_(1.0f + fex2_(-1.4426950408889634f * t));
}

// -------- precompute --------
__global__ void prep_m(const float* __restrict__ W) {
    int i = blockIdx.x * 256 + threadIdx.x;   // over H*D, W row-major [H][D]
    int h = i >> 10, d = i & 1023;
    g_mTab[d * HH + h] = __expf(-W[i]);
}
__global__ void prep_xb(const float* __restrict__ x) {
    int gtid = blockIdx.x * 256 + threadIdx.x;
    int warp = gtid >> 5, lane = gtid & 31;
    int b = warp >> 5, ch = warp & 31;
    float v = x[b * DD + ch * 32 + lane];
    unsigned m = __ballot_sync(0xffffffffu, v != 0.0f);
    if (lane == 0) g_xb[b * 32 + ch] = m;
}
__global__ void prep_r(const float* __restrict__ c) {
    int h = blockIdx.x * 256 + threadIdx.x;
    if (h < HH) {
        float cv = c[h];
        g_rinit[h] = 1.0f / (1.0f + __expf(-cv));
        g_sinit[h] = __expf(-cv);
    }
}

// -------- main: warp = 1 batch row, lane owns 32 h-values --------
// State per lane: s = exp(-a) (16 f32x2 pairs), r = sigmoid(a) (16 pairs).
// Step d:  partial_d = per-lane r.V[d];  if x: s *= m[d]; r = rcp(1+s).
// Reductions for 4 steps are done together (interleaved butterflies) so their
// SHFL latency is off the recurrence critical path.
__global__ void __launch_bounds__(256, 2)
nade_main(const float* __restrict__ V, const float* __restrict__ bvec,
          float* __restrict__ out) {
    __shared__ float sB[DD];
    const int tid = threadIdx.x, lane = tid & 31, wid = tid >> 5;
    const int b = blockIdx.x * 8 + wid;

    for (int i = tid; i < DD; i += 256) sB[i] = bvec[i];
    __syncthreads();

    u64 r2[16], s2[16];
    #pragma unroll
    for (int q = 0; q < 8; ++q) {
        const int hb = (lane + 32 * q) * 4;
        float4 rv = *reinterpret_cast<const float4*>(&g_rinit[hb]);
        float4 sv = *reinterpret_cast<const float4*>(&g_sinit[hb]);
        r2[2*q]   = pack2_(rv.x, rv.y);  r2[2*q+1] = pack2_(rv.z, rv.w);
        s2[2*q]   = pack2_(sv.x, sv.y);  s2[2*q+1] = pack2_(sv.z, sv.w);
    }

    const u64 ONE2 = 0x3f8000003f800000ULL;
    unsigned bits = 0;
    float pp[4];

    #pragma unroll 1
    for (int d4 = 0; d4 < DD / 4; ++d4) {
        if ((d4 & 7) == 0) bits = g_xb[b * 32 + (d4 >> 3)];

        #pragma unroll
        for (int k = 0; k < 4; ++k) {
            const int d = d4 * 4 + k;

            // dot partial: per-lane sum of r[h] * V[d][h]  (8x LDG.128)
            const ulonglong2* vrow = reinterpret_cast<const ulonglong2*>(V + d * HH);
            u64 acc0 = 0ULL, acc1 = 0ULL;
            #pragma unroll
            for (int q = 0; q < 8; ++q) {
                const ulonglong2 v = __ldg(&vrow[lane + 32 * q]);
                acc0 = fma2_(r2[2*q],   v.x, acc0);
                acc1 = fma2_(r2[2*q+1], v.y, acc1);
            }
            acc0 = add2_(acc0, acc1);
            float sa, sb_; unpack2_(acc0, sa, sb_);
            pp[k] = sa + sb_;

            // state update (warp-uniform branch, prob 1/2)
            if (bits & (1u << (d & 31))) {
                const ulonglong2* mrow = reinterpret_cast<const ulonglong2*>(g_mTab + d * HH);
                #pragma unroll
                for (int q = 0; q < 8; ++q) {
                    const ulonglong2 m = __ldg(&mrow[lane + 32 * q]);
                    s2[2*q]   = mul2_(s2[2*q],   m.x);
                    s2[2*q+1] = mul2_(s2[2*q+1], m.y);
                    float d0, d1, d2, d3;
                    unpack2_(add2_(ONE2, s2[2*q]),   d0, d1);
                    unpack2_(add2_(ONE2, s2[2*q+1]), d2, d3);
                    r2[2*q]   = pack2_(frcp_(d0), frcp_(d1));
                    r2[2*q+1] = pack2_(frcp_(d2), frcp_(d3));
                }
            }
        }

        // reduce 4 partials together: butterflies interleaved for ILP
        #pragma unroll
        for (int off = 16; off; off >>= 1) {
            pp[0] += __shfl_xor_sync(0xffffffffu, pp[0], off);
            pp[1] += __shfl_xor_sync(0xffffffffu, pp[1], off);
            pp[2] += __shfl_xor_sync(0xffffffffu, pp[2], off);
            pp[3] += __shfl_xor_sync(0xffffffffu, pp[3], off);
        }

        if (lane == 0) {
            const int d0 = d4 * 4;
            float4 o = make_float4(sigm_(sB[d0]     + pp[0]),
                                   sigm_(sB[d0 + 1] + pp[1]),
                                   sigm_(sB[d0 + 2] + pp[2]),
                                   sigm_(sB[d0 + 3] + pp[3]));
            *reinterpret_cast<float4*>(&out[(unsigned)b * DD + d0]) = o;
        }
    }
}

extern "C" void kernel_launch(void* const* d_in, const int* in_sizes, int n_in,
                              void* d_out, int out_size) {
    const float* x = (const float*)d_in[0];   // (B, D)
    const float* V = (const float*)d_in[1];   // (D, H)
    const float* b = (const float*)d_in[2];   // (D,)
    const float* W = (const float*)d_in[3];   // (H, D)
    const float* c = (const float*)d_in[4];   // (H,)
    float* out = (float*)d_out;               // (B, D)

    prep_m <<<(HH * DD) / 256, 256>>>(W);
    prep_xb<<<(BB * 32 * 32) / 256, 256>>>(x);
    prep_r <<<HH / 256, 256>>>(c);
    nade_main<<<BB / 8, 256>>>(V, b, out);
}

// round 6
// speedup vs baseline: 1.5467x; 1.0227x over previous
#include <cuda_runtime.h>
#include <cuda_bf16.h>

#define DD 1024
#define HH 1024
#define BB 8192

__device__ __align__(16) float g_mTab[DD * HH];  // m[d][h] = exp(-W[h][d])
__device__ unsigned            g_xb[BB * 32];    // packed x bits [b][d/32]
__device__ __align__(16) float g_rinit[HH];      // sigmoid(c[h])

typedef unsigned long long u64;

__device__ __forceinline__ u64 fma2_(u64 a, u64 b, u64 c) {
    u64 d; asm("fma.rn.f32x2 %0, %1, %2, %3;" : "=l"(d) : "l"(a), "l"(b), "l"(c)); return d;
}
__device__ __forceinline__ u64 mul2_(u64 a, u64 b) {
    u64 d; asm("mul.rn.f32x2 %0, %1, %2;" : "=l"(d) : "l"(a), "l"(b)); return d;
}
__device__ __forceinline__ u64 add2_(u64 a, u64 b) {
    u64 d; asm("add.rn.f32x2 %0, %1, %2;" : "=l"(d) : "l"(a), "l"(b)); return d;
}
__device__ __forceinline__ float frcp_(float x) {
    float r; asm("rcp.approx.f32 %0, %1;" : "=f"(r) : "f"(x)); return r;
}
__device__ __forceinline__ float fex2_(float x) {
    float r; asm("ex2.approx.f32 %0, %1;" : "=f"(r) : "f"(x)); return r;
}
__device__ __forceinline__ u64 pack2_(float lo, float hi) {
    u64 u; asm("mov.b64 %0, {%1, %2};" : "=l"(u) : "f"(lo), "f"(hi)); return u;
}
__device__ __forceinline__ void unpack2_(u64 u, float& a, float& b) {
    asm("mov.b64 {%0, %1}, %2;" : "=f"(a), "=f"(b) : "l"(u));
}
__device__ __forceinline__ float sigm_(float t) {
    return frcp_(1.0f + fex2_(-1.4426950408889634f * t));
}

#define ONE2 0x3f8000003f800000ULL
#define SGN2 0x8000000080000000ULL

// r' = sigma(a + w) given r = sigma(a), m = exp(-w):
//   r' = r / (r + m*(1-r))
__device__ __forceinline__ void upd_(u64& r, u64 m) {
    u64 u   = add2_(ONE2, r ^ SGN2);      // 1 - r
    u64 den = fma2_(m, u, r);             // r + m*(1-r)
    float d0, d1; unpack2_(den, d0, d1);
    r = mul2_(r, pack2_(frcp_(d0), frcp_(d1)));
}

// -------- precompute --------
__global__ void prep_m(const float* __restrict__ W) {
    int i = blockIdx.x * 256 + threadIdx.x;   // over H*D, W row-major [H][D]
    int h = i >> 10, d = i & 1023;
    g_mTab[d * HH + h] = __expf(-W[i]);
}
__global__ void prep_xb(const float* __restrict__ x) {
    int gtid = blockIdx.x * 256 + threadIdx.x;
    int warp = gtid >> 5, lane = gtid & 31;
    int b = warp >> 5, ch = warp & 31;
    float v = x[b * DD + ch * 32 + lane];
    unsigned m = __ballot_sync(0xffffffffu, v != 0.0f);
    if (lane == 0) g_xb[b * 32 + ch] = m;
}
__global__ void prep_r(const float* __restrict__ c) {
    int h = blockIdx.x * 256 + threadIdx.x;
    if (h < HH) g_rinit[h] = 1.0f / (1.0f + __expf(-c[h]));
}

// -------- main: warp = 2 batch rows, lane owns 32 h-values per row --------
// State: r = sigmoid(a), 16 f32x2 pairs per row (V loads amortized over 2 rows).
// Per 32-step block: partials go to a warp-private padded smem transpose buffer;
// the reduction + sigmoid + coalesced store happen once per block per row.
__global__ void __launch_bounds__(128, 4)
nade_main(const float* __restrict__ V, const float* __restrict__ bvec,
          float* __restrict__ out) {
    __shared__ float sP[4][2][32 * 33];   // [warp][row][step*33 + lane]
    const int tid = threadIdx.x, lane = tid & 31, wid = tid >> 5;
    const int b0 = blockIdx.x * 8 + wid * 2;

    float* P0 = &sP[wid][0][0];
    float* P1 = &sP[wid][1][0];

    u64 r0[16], r1[16];
    #pragma unroll
    for (int q = 0; q < 8; ++q) {
        const int hb = (lane + 32 * q) * 4;
        float4 rv = *reinterpret_cast<const float4*>(&g_rinit[hb]);
        r0[2*q]   = pack2_(rv.x, rv.y);  r0[2*q+1] = pack2_(rv.z, rv.w);
        r1[2*q]   = r0[2*q];             r1[2*q+1] = r0[2*q+1];
    }

    #pragma unroll 1
    for (int blk = 0; blk < 32; ++blk) {
        const unsigned bits0 = g_xb[(unsigned)b0 * 32 + blk];
        const unsigned bits1 = g_xb[(unsigned)(b0 + 1) * 32 + blk];
        const unsigned bor = bits0 | bits1;

        #pragma unroll 1
        for (int k = 0; k < 32; ++k) {
            const int d = blk * 32 + k;

            // shared dot: one V row feeds both batch rows
            const ulonglong2* vrow = reinterpret_cast<const ulonglong2*>(V + d * HH);
            u64 a00 = 0ULL, a01 = 0ULL, a10 = 0ULL, a11 = 0ULL;
            #pragma unroll
            for (int q = 0; q < 8; ++q) {
                const ulonglong2 v = __ldg(&vrow[lane + 32 * q]);
                a00 = fma2_(r0[2*q],   v.x, a00);
                a01 = fma2_(r0[2*q+1], v.y, a01);
                a10 = fma2_(r1[2*q],   v.x, a10);
                a11 = fma2_(r1[2*q+1], v.y, a11);
            }
            a00 = add2_(a00, a01);
            a10 = add2_(a10, a11);
            float x0, x1; unpack2_(a00, x0, x1); P0[k * 33 + lane] = x0 + x1;
            float y0, y1; unpack2_(a10, y0, y1); P1[k * 33 + lane] = y0 + y1;

            // shared m row; per-row conditional update (warp-uniform branches)
            if ((bor >> k) & 1u) {
                const ulonglong2* mrow = reinterpret_cast<const ulonglong2*>(g_mTab + d * HH);
                const bool u0 = (bits0 >> k) & 1u;
                const bool u1 = (bits1 >> k) & 1u;
                #pragma unroll
                for (int q = 0; q < 8; ++q) {
                    const ulonglong2 m = __ldg(&mrow[lane + 32 * q]);
                    if (u0) { upd_(r0[2*q], m.x); upd_(r0[2*q+1], m.y); }
                    if (u1) { upd_(r1[2*q], m.x); upd_(r1[2*q+1], m.y); }
                }
            }
        }

        __syncwarp();
        // lane l sums the 32 partials of step l (conflict-free: stride 33)
        float s0 = 0.0f, s1 = 0.0f;
        #pragma unroll
        for (int j = 0; j < 32; ++j) {
            s0 += P0[lane * 33 + j];
            s1 += P1[lane * 33 + j];
        }
        const int d0 = blk * 32 + lane;
        const float bb = __ldg(&bvec[d0]);
        out[(unsigned)b0 * DD + d0]       = sigm_(bb + s0);
        out[(unsigned)(b0 + 1) * DD + d0] = sigm_(bb + s1);
        __syncwarp();
    }
}

extern "C" void kernel_launch(void* const* d_in, const int* in_sizes, int n_in,
                              void* d_out, int out_size) {
    const float* x = (const float*)d_in[0];   // (B, D)
    const float* V = (const float*)d_in[1];   // (D, H)
    const float* b = (const float*)d_in[2];   // (D,)
    const float* W = (const float*)d_in[3];   // (H, D)
    const float* c = (const float*)d_in[4];   // (H,)
    float* out = (float*)d_out;               // (B, D)

    prep_m <<<(HH * DD) / 256, 256>>>(W);
    prep_xb<<<(BB * 32 * 32) / 256, 256>>>(x);
    prep_r <<<HH / 256, 256>>>(c);
    nade_main<<<BB / 8, 128>>>(V, b, out);
}

// round 8
// speedup vs baseline: 2.0783x; 1.3437x over previous
#include <cuda_runtime.h>
#include <cuda_bf16.h>

#define DD 1024
#define HH 1024
#define BB 8192

__device__ __align__(16) float g_twTab[DD * HH]; // tw[d][h] = tanh(W[h][d]/2)
__device__ unsigned            g_xb[BB * 32];    // packed x bits [b][d/32]
__device__ __align__(16) float g_tinit[HH];      // tanh(c[h]/2)
__device__ __align__(16) float g_B2[DD];         // b[d] + 0.5*rowsum(V[d])

typedef unsigned long long u64;

__device__ __forceinline__ u64 fma2_(u64 a, u64 b, u64 c) {
    u64 d; asm("fma.rn.f32x2 %0, %1, %2, %3;" : "=l"(d) : "l"(a), "l"(b), "l"(c)); return d;
}
__device__ __forceinline__ u64 mul2_(u64 a, u64 b) {
    u64 d; asm("mul.rn.f32x2 %0, %1, %2;" : "=l"(d) : "l"(a), "l"(b)); return d;
}
__device__ __forceinline__ u64 add2_(u64 a, u64 b) {
    u64 d; asm("add.rn.f32x2 %0, %1, %2;" : "=l"(d) : "l"(a), "l"(b)); return d;
}
__device__ __forceinline__ float frcp_(float x) {
    float r; asm("rcp.approx.f32 %0, %1;" : "=f"(r) : "f"(x)); return r;
}
__device__ __forceinline__ float fex2_(float x) {
    float r; asm("ex2.approx.f32 %0, %1;" : "=f"(r) : "f"(x)); return r;
}
__device__ __forceinline__ void unpack2_(u64 u, float& a, float& b) {
    asm("mov.b64 {%0, %1}, %2;" : "=f"(a), "=f"(b) : "l"(u));
}
__device__ __forceinline__ float sigm_(float t) {
    return frcp_(1.0f + fex2_(-1.4426950408889634f * t));
}

#define ONE2 0x3f8000003f800000ULL
#define SGN2 0x8000000080000000ULL

// tanh-space update: tau' = (tau + tw) / (1 + tau*tw), |tau*tw| <= ~0.083.
// 1/(1+z) = 1 + zn + zn^2 + zn^3 + zn^4 (zn = -z), deg-4 Horner. No MUFU.
__device__ __forceinline__ void upd_(u64& tau, u64 tw) {
    u64 zn  = mul2_(tau, tw) ^ SGN2;       // -tau*tw
    u64 num = add2_(tau, tw);              // tau + tw
    u64 p   = add2_(ONE2, zn);             // 1 + zn
    p = fma2_(zn, p, ONE2);
    p = fma2_(zn, p, ONE2);
    p = fma2_(zn, p, ONE2);                // deg-4
    tau = mul2_(num, p);
}

// -------- precompute --------
__global__ void prep_tw(const float* __restrict__ W) {
    int i = blockIdx.x * 256 + threadIdx.x;   // over H*D, W row-major [H][D]
    int h = i >> 10, d = i & 1023;
    g_twTab[d * HH + h] = tanhf(0.5f * W[i]);
}
__global__ void prep_xb(const float* __restrict__ x) {
    int gtid = blockIdx.x * 256 + threadIdx.x;
    int warp = gtid >> 5, lane = gtid & 31;
    int b = warp >> 5, ch = warp & 31;
    float v = x[b * DD + ch * 32 + lane];
    unsigned m = __ballot_sync(0xffffffffu, v != 0.0f);
    if (lane == 0) g_xb[b * 32 + ch] = m;
}
__global__ void prep_tc(const float* __restrict__ c) {
    int h = blockIdx.x * 256 + threadIdx.x;
    if (h < HH) g_tinit[h] = tanhf(0.5f * c[h]);
}
__global__ void prep_B2(const float* __restrict__ V, const float* __restrict__ bvec) {
    // one warp per d-row: rowsum of V[d,:]
    int warp = (blockIdx.x * 256 + threadIdx.x) >> 5;
    int lane = threadIdx.x & 31;
    float s = 0.0f;
    const float4* row = reinterpret_cast<const float4*>(V + warp * HH);
    #pragma unroll
    for (int q = 0; q < 8; ++q) {
        float4 v = row[lane + 32 * q];
        s += (v.x + v.y) + (v.z + v.w);
    }
    #pragma unroll
    for (int off = 16; off; off >>= 1) s += __shfl_xor_sync(0xffffffffu, s, off);
    if (lane == 0) g_B2[warp] = bvec[warp] + 0.5f * s;
}

// -------- main: warp = 2 batch rows, lane owns 32 h-values per row --------
__global__ void __launch_bounds__(128, 4)
nade_main(const float* __restrict__ V, float* __restrict__ out) {
    __shared__ float sP[4][2][32 * 33];   // [warp][row][step*33 + lane]
    const int tid = threadIdx.x, lane = tid & 31, wid = tid >> 5;
    const int b0 = blockIdx.x * 8 + wid * 2;

    float* P0 = &sP[wid][0][0];
    float* P1 = &sP[wid][1][0];

    u64 t0[16], t1[16];
    #pragma unroll
    for (int q = 0; q < 8; ++q) {
        const int hb = (lane + 32 * q) * 4;
        const u64* ti = reinterpret_cast<const u64*>(&g_tinit[hb]);
        t0[2*q] = ti[0];  t0[2*q+1] = ti[1];
        t1[2*q] = ti[0];  t1[2*q+1] = ti[1];
    }

    #pragma unroll 1
    for (int blk = 0; blk < 32; ++blk) {
        const unsigned bits0 = g_xb[(unsigned)b0 * 32 + blk];
        const unsigned bits1 = g_xb[(unsigned)(b0 + 1) * 32 + blk];
        const unsigned bor = bits0 | bits1;

        #pragma unroll 1
        for (int k = 0; k < 32; ++k) {
            const int d = blk * 32 + k;

            // shared dot: one V row feeds both batch rows (tau-dot)
            const ulonglong2* vrow = reinterpret_cast<const ulonglong2*>(V + d * HH);
            u64 a00 = 0ULL, a01 = 0ULL, a10 = 0ULL, a11 = 0ULL;
            #pragma unroll
            for (int q = 0; q < 8; ++q) {
                const ulonglong2 v = __ldg(&vrow[lane + 32 * q]);
                a00 = fma2_(t0[2*q],   v.x, a00);
                a01 = fma2_(t0[2*q+1], v.y, a01);
                a10 = fma2_(t1[2*q],   v.x, a10);
                a11 = fma2_(t1[2*q+1], v.y, a11);
            }
            a00 = add2_(a00, a01);
            a10 = add2_(a10, a11);
            float x0, x1; unpack2_(a00, x0, x1); P0[k * 33 + lane] = x0 + x1;
            float y0, y1; unpack2_(a10, y0, y1); P1[k * 33 + lane] = y0 + y1;

            // shared tw row; per-row conditional update (warp-uniform branches)
            if ((bor >> k) & 1u) {
                const ulonglong2* trow = reinterpret_cast<const ulonglong2*>(g_twTab + d * HH);
                const bool u0 = (bits0 >> k) & 1u;
                const bool u1 = (bits1 >> k) & 1u;
                #pragma unroll
                for (int q = 0; q < 8; ++q) {
                    const ulonglong2 tw = __ldg(&trow[lane + 32 * q]);
                    if (u0) { upd_(t0[2*q], tw.x); upd_(t0[2*q+1], tw.y); }
                    if (u1) { upd_(t1[2*q], tw.x); upd_(t1[2*q+1], tw.y); }
                }
            }
        }

        __syncwarp();
        // lane l sums the 32 partials of step l (conflict-free: stride 33)
        float s0 = 0.0f, s1 = 0.0f;
        #pragma unroll
        for (int j = 0; j < 32; ++j) {
            s0 += P0[lane * 33 + j];
            s1 += P1[lane * 33 + j];
        }
        const int d0 = blk * 32 + lane;
        const float bb = __ldg(&g_B2[d0]);
        out[(unsigned)b0 * DD + d0]       = sigm_(fmaf(s0, 0.5f, bb));
        out[(unsigned)(b0 + 1) * DD + d0] = sigm_(fmaf(s1, 0.5f, bb));
        __syncwarp();
    }
}

extern "C" void kernel_launch(void* const* d_in, const int* in_sizes, int n_in,
                              void* d_out, int out_size) {
    const float* x = (const float*)d_in[0];   // (B, D)
    const float* V = (const float*)d_in[1];   // (D, H)
    const float* b = (const float*)d_in[2];   // (D,)
    const float* W = (const float*)d_in[3];   // (H, D)
    const float* c = (const float*)d_in[4];   // (H,)
    float* out = (float*)d_out;               // (B, D)

    prep_tw<<<(HH * DD) / 256, 256>>>(W);
    prep_xb<<<(BB * 32 * 32) / 256, 256>>>(x);
    prep_tc<<<HH / 256, 256>>>(c);
    prep_B2<<<(DD * 32) / 256, 256>>>(V, b);
    nade_main<<<BB / 8, 128>>>(V, out);
}

// round 10
// speedup vs baseline: 2.2373x; 1.0765x over previous
#include <cuda_runtime.h>
#include <cuda_bf16.h>

#define DD 1024
#define HH 1024
#define BB 8192

__device__ __align__(16) float g_twTab[DD * HH]; // tw[d][h] = tanh(W[h][d]/2)
__device__ unsigned            g_xb[BB * 32];    // packed x bits [b][d/32]
__device__ __align__(16) float g_tinit[HH];      // tanh(c[h]/2)
__device__ __align__(16) float g_B2[DD];         // b[d] + 0.5*rowsum(V[d])

typedef unsigned long long u64;

__device__ __forceinline__ u64 fma2_(u64 a, u64 b, u64 c) {
    u64 d; asm("fma.rn.f32x2 %0, %1, %2, %3;" : "=l"(d) : "l"(a), "l"(b), "l"(c)); return d;
}
__device__ __forceinline__ u64 mul2_(u64 a, u64 b) {
    u64 d; asm("mul.rn.f32x2 %0, %1, %2;" : "=l"(d) : "l"(a), "l"(b)); return d;
}
__device__ __forceinline__ u64 add2_(u64 a, u64 b) {
    u64 d; asm("add.rn.f32x2 %0, %1, %2;" : "=l"(d) : "l"(a), "l"(b)); return d;
}
__device__ __forceinline__ float frcp_(float x) {
    float r; asm("rcp.approx.f32 %0, %1;" : "=f"(r) : "f"(x)); return r;
}
__device__ __forceinline__ float fex2_(float x) {
    float r; asm("ex2.approx.f32 %0, %1;" : "=f"(r) : "f"(x)); return r;
}
__device__ __forceinline__ void unpack2_(u64 u, float& a, float& b) {
    asm("mov.b64 {%0, %1}, %2;" : "=f"(a), "=f"(b) : "l"(u));
}
__device__ __forceinline__ float sigm_(float t) {
    return frcp_(1.0f + fex2_(-1.4426950408889634f * t));
}

#define ONE2 0x3f8000003f800000ULL
#define SGN2 0x8000000080000000ULL

// tanh addition law: tau' = (tau + tw) / (1 + tau*tw), |tau*tw| <= ~0.083.
// 1/(1+z) via deg-3 Horner in zn = -z (err <= z^4 ~ 4.7e-5 worst, ~1e-7 typ).
__device__ __forceinline__ void upd_(u64& tau, u64 tw) {
    u64 zn  = mul2_(tau, tw) ^ SGN2;
    u64 num = add2_(tau, tw);
    u64 p   = add2_(ONE2, zn);
    p = fma2_(zn, p, ONE2);
    p = fma2_(zn, p, ONE2);               // 1 + zn + zn^2 + zn^3
    tau = mul2_(num, p);
}

// -------- precompute --------
__global__ void prep_tw(const float* __restrict__ W) {
    int i = blockIdx.x * 256 + threadIdx.x;   // over H*D, W row-major [H][D]
    int h = i >> 10, d = i & 1023;
    g_twTab[d * HH + h] = tanhf(0.5f * W[i]);
}
__global__ void prep_xb(const float* __restrict__ x) {
    int gtid = blockIdx.x * 256 + threadIdx.x;
    int warp = gtid >> 5, lane = gtid & 31;
    int b = warp >> 5, ch = warp & 31;
    float v = x[b * DD + ch * 32 + lane];
    unsigned m = __ballot_sync(0xffffffffu, v != 0.0f);
    if (lane == 0) g_xb[b * 32 + ch] = m;
}
__global__ void prep_tc(const float* __restrict__ c) {
    int h = blockIdx.x * 256 + threadIdx.x;
    if (h < HH) g_tinit[h] = tanhf(0.5f * c[h]);
}
__global__ void prep_B2(const float* __restrict__ V, const float* __restrict__ bvec) {
    int warp = (blockIdx.x * 256 + threadIdx.x) >> 5;
    int lane = threadIdx.x & 31;
    float s = 0.0f;
    const float4* row = reinterpret_cast<const float4*>(V + warp * HH);
    #pragma unroll
    for (int q = 0; q < 8; ++q) {
        float4 v = row[lane + 32 * q];
        s += (v.x + v.y) + (v.z + v.w);
    }
    #pragma unroll
    for (int off = 16; off; off >>= 1) s += __shfl_xor_sync(0xffffffffu, s, off);
    if (lane == 0) g_B2[warp] = bvec[warp] + 0.5f * s;
}

// -------- main --------
// Warp PAIR owns 2 batch rows; within the pair, warp (wid&1) owns h-half
// [half*512, half*512+512). tau state = 8 u64 per row per warp (16 regs).
// Per 16-step block: per-lane partials -> padded smem; even warp of the pair
// reduces 2 rows x 16 steps (sum over 64 lanes), applies sigmoid, stores.
__global__ void __launch_bounds__(256, 3)
nade_main(const float* __restrict__ V, float* __restrict__ out) {
    __shared__ float sP[8][2 * 528];          // [warp][row*528 + k*33 + lane]
    const int tid = threadIdx.x, lane = tid & 31, wid = tid >> 5;
    const int pair = wid >> 1, half = wid & 1;
    const int b0 = blockIdx.x * 8 + pair * 2;
    const int hoff = half * 512;

    u64 t0[8], t1[8];
    #pragma unroll
    for (int q = 0; q < 4; ++q) {
        const u64* ti = reinterpret_cast<const u64*>(&g_tinit[hoff + (lane + 32 * q) * 4]);
        t0[2*q] = ti[0];  t0[2*q+1] = ti[1];
        t1[2*q] = ti[0];  t1[2*q+1] = ti[1];
    }

    float* P = sP[wid];
    unsigned xw0 = 0, xw1 = 0;

    #pragma unroll 1
    for (int blk = 0; blk < 64; ++blk) {
        if ((blk & 1) == 0) {
            xw0 = g_xb[(unsigned)b0 * 32 + (blk >> 1)];
            xw1 = g_xb[(unsigned)(b0 + 1) * 32 + (blk >> 1)];
        }

        #pragma unroll 1
        for (int k = 0; k < 16; ++k) {
            const int d = blk * 16 + k;

            // dot partial over this warp's 512 h's, both rows share V loads
            const ulonglong2* vrow = reinterpret_cast<const ulonglong2*>(V + d * HH + hoff);
            u64 a00 = 0ULL, a01 = 0ULL, a10 = 0ULL, a11 = 0ULL;
            #pragma unroll
            for (int q = 0; q < 4; ++q) {
                const ulonglong2 v = __ldg(&vrow[lane + 32 * q]);
                a00 = fma2_(t0[2*q],   v.x, a00);
                a01 = fma2_(t0[2*q+1], v.y, a01);
                a10 = fma2_(t1[2*q],   v.x, a10);
                a11 = fma2_(t1[2*q+1], v.y, a11);
            }
            a00 = add2_(a00, a01);
            a10 = add2_(a10, a11);
            float x0, x1; unpack2_(a00, x0, x1); P[k * 33 + lane]       = x0 + x1;
            float y0, y1; unpack2_(a10, y0, y1); P[528 + k * 33 + lane] = y0 + y1;

            // conditional tanh-space update (warp-uniform branches)
            const unsigned bit = 1u << (d & 31);
            if ((xw0 | xw1) & bit) {
                const ulonglong2* trow = reinterpret_cast<const ulonglong2*>(g_twTab + d * HH + hoff);
                const bool u0 = (xw0 & bit) != 0u;
                const bool u1 = (xw1 & bit) != 0u;
                #pragma unroll
                for (int q = 0; q < 4; ++q) {
                    const ulonglong2 tw = __ldg(&trow[lane + 32 * q]);
                    if (u0) { upd_(t0[2*q], tw.x); upd_(t0[2*q+1], tw.y); }
                    if (u1) { upd_(t1[2*q], tw.x); upd_(t1[2*q+1], tw.y); }
                }
            }
        }

        __syncthreads();
        if ((wid & 1) == 0) {
            // 32 items = 2 rows x 16 steps; lane -> (row, step)
            const int row = lane >> 4, step = lane & 15;
            const float* A  = sP[wid]     + row * 528 + step * 33;
            const float* Bp = sP[wid + 1] + row * 528 + step * 33;
            float s = 0.0f;
            #pragma unroll
            for (int j = 0; j < 32; ++j) s += A[j] + Bp[j];
            const int d0 = blk * 16 + step;
            const float bb = __ldg(&g_B2[d0]);
            out[(unsigned)(b0 + row) * DD + d0] = sigm_(fmaf(s, 0.5f, bb));
        }
        __syncthreads();
    }
}

extern "C" void kernel_launch(void* const* d_in, const int* in_sizes, int n_in,
                              void* d_out, int out_size) {
    const float* x = (const float*)d_in[0];   // (B, D)
    const float* V = (const float*)d_in[1];   // (D, H)
    const float* b = (const float*)d_in[2];   // (D,)
    const float* W = (const float*)d_in[3];   // (H, D)
    const float* c = (const float*)d_in[4];   // (H,)
    float* out = (float*)d_out;               // (B, D)

    prep_tw<<<(HH * DD) / 256, 256>>>(W);
    prep_xb<<<(BB * 32 * 32) / 256, 256>>>(x);
    prep_tc<<<HH / 256, 256>>>(c);
    prep_B2<<<(DD * 32) / 256, 256>>>(V, b);
    nade_main<<<BB / 8, 256>>>(V, out);
}

// round 14
// speedup vs baseline: 2.3100x; 1.0325x over previous
#include <cuda_runtime.h>
#include <cuda_bf16.h>

#define DD 1024
#define HH 1024
#define BB 8192

__device__ __align__(16) float g_twTab[DD * HH]; // tw[d][h] = tanh(W[h][d]/2)
__device__ unsigned            g_xb[BB * 32];    // packed x bits [b][d/32]
__device__ __align__(16) float g_tinit[HH];      // tanh(c[h]/2)
__device__ __align__(16) float g_B2[DD];         // b[d] + 0.5*rowsum(V[d])

typedef unsigned long long u64;

__device__ __forceinline__ u64 fma2_(u64 a, u64 b, u64 c) {
    u64 d; asm("fma.rn.f32x2 %0, %1, %2, %3;" : "=l"(d) : "l"(a), "l"(b), "l"(c)); return d;
}
__device__ __forceinline__ u64 mul2_(u64 a, u64 b) {
    u64 d; asm("mul.rn.f32x2 %0, %1, %2;" : "=l"(d) : "l"(a), "l"(b)); return d;
}
__device__ __forceinline__ u64 add2_(u64 a, u64 b) {
    u64 d; asm("add.rn.f32x2 %0, %1, %2;" : "=l"(d) : "l"(a), "l"(b)); return d;
}
__device__ __forceinline__ float frcp_(float x) {
    float r; asm("rcp.approx.f32 %0, %1;" : "=f"(r) : "f"(x)); return r;
}
__device__ __forceinline__ float fex2_(float x) {
    float r; asm("ex2.approx.f32 %0, %1;" : "=f"(r) : "f"(x)); return r;
}
__device__ __forceinline__ void unpack2_(u64 u, float& a, float& b) {
    asm("mov.b64 {%0, %1}, %2;" : "=f"(a), "=f"(b) : "l"(u));
}
__device__ __forceinline__ float sigm_(float t) {
    return frcp_(1.0f + fex2_(-1.4426950408889634f * t));
}

#define ONE2 0x3f8000003f800000ULL
#define SGN2 0x8000000080000000ULL

// tanh addition law: tau' = (tau + tw)/(1 + tau*tw), |tau*tw| <= ~0.083.
// 1/(1+z) via deg-3 Horner in zn = -z. No MUFU.
__device__ __forceinline__ void upd_(u64& tau, u64 tw) {
    u64 zn  = mul2_(tau, tw) ^ SGN2;
    u64 num = add2_(tau, tw);
    u64 p   = add2_(ONE2, zn);
    p = fma2_(zn, p, ONE2);
    p = fma2_(zn, p, ONE2);
    tau = mul2_(num, p);
}

__device__ __forceinline__ void ldg4_(u64* dst, const float* base, int lane) {
    const ulonglong2* p = reinterpret_cast<const ulonglong2*>(base);
    #pragma unroll
    for (int q = 0; q < 4; ++q) {
        ulonglong2 v = __ldg(&p[lane + 32 * q]);
        dst[2*q] = v.x; dst[2*q+1] = v.y;
    }
}

// -------- precompute --------
__global__ void prep_tw(const float* __restrict__ W) {
    int i = blockIdx.x * 256 + threadIdx.x;   // over H*D, W row-major [H][D]
    int h = i >> 10, d = i & 1023;
    g_twTab[d * HH + h] = tanhf(0.5f * W[i]);
}
__global__ void prep_xb(const float* __restrict__ x) {
    int gtid = blockIdx.x * 256 + threadIdx.x;
    int warp = gtid >> 5, lane = gtid & 31;
    int b = warp >> 5, ch = warp & 31;
    float v = x[b * DD + ch * 32 + lane];
    unsigned m = __ballot_sync(0xffffffffu, v != 0.0f);
    if (lane == 0) g_xb[b * 32 + ch] = m;
}
__global__ void prep_tc(const float* __restrict__ c) {
    int h = blockIdx.x * 256 + threadIdx.x;
    if (h < HH) g_tinit[h] = tanhf(0.5f * c[h]);
}
__global__ void prep_B2(const float* __restrict__ V, const float* __restrict__ bvec) {
    int warp = (blockIdx.x * 256 + threadIdx.x) >> 5;
    int lane = threadIdx.x & 31;
    float s = 0.0f;
    const float4* row = reinterpret_cast<const float4*>(V + warp * HH);
    #pragma unroll
    for (int q = 0; q < 8; ++q) {
        float4 v = row[lane + 32 * q];
        s += (v.x + v.y) + (v.z + v.w);
    }
    #pragma unroll
    for (int off = 16; off; off >>= 1) s += __shfl_xor_sync(0xffffffffu, s, off);
    if (lane == 0) g_B2[warp] = bvec[warp] + 0.5f * s;
}

// one pipelined step: consumes vc (V row d), prefetches vn (V row d+1)
__device__ __forceinline__ void step_(
    int d, int bitpos, int k,
    u64 (&vc)[8], u64 (&vn)[8], u64 (&t0)[8], u64 (&t1)[8],
    unsigned xw0, unsigned xw1,
    const float* __restrict__ V, const float* __restrict__ TW,
    int hoff, int lane, float* P)
{
    const unsigned bit = 1u << bitpos;
    const bool u0 = (xw0 & bit) != 0u;
    const bool u1 = (xw1 & bit) != 0u;

    // issue tw load early (bit known in advance; warp-uniform)
    u64 tw[8];
    if (u0 | u1) ldg4_(tw, TW + (size_t)d * HH + hoff, lane);
    // prefetch next V row (wraps harmlessly at d=1023)
    ldg4_(vn, V + (size_t)((d + 1) & (DD - 1)) * HH + hoff, lane);

    // dot partials for both rows from vc
    u64 a00 = 0ULL, a01 = 0ULL, a10 = 0ULL, a11 = 0ULL;
    #pragma unroll
    for (int q = 0; q < 4; ++q) {
        a00 = fma2_(t0[2*q],   vc[2*q],   a00);
        a01 = fma2_(t0[2*q+1], vc[2*q+1], a01);
        a10 = fma2_(t1[2*q],   vc[2*q],   a10);
        a11 = fma2_(t1[2*q+1], vc[2*q+1], a11);
    }
    a00 = add2_(a00, a01);
    a10 = add2_(a10, a11);
    float x0, x1; unpack2_(a00, x0, x1); P[k * 33 + lane]       = x0 + x1;
    float y0, y1; unpack2_(a10, y0, y1); P[528 + k * 33 + lane] = y0 + y1;

    if (u0) {
        #pragma unroll
        for (int q = 0; q < 8; ++q) upd_(t0[q], tw[q]);
    }
    if (u1) {
        #pragma unroll
        for (int q = 0; q < 8; ++q) upd_(t1[q], tw[q]);
    }
}

// -------- main --------
// Warp PAIR owns 2 batch rows; warp (wid&1) owns h-half [half*512, +512).
// V row register-pipelined (ping-pong). Pair-scoped named barriers; both
// warps of a pair reduce (even -> row0, odd -> row1).
__global__ void __launch_bounds__(256, 2)
nade_main(const float* __restrict__ V, float* __restrict__ out) {
    __shared__ float sP[8][2 * 528];          // [warp][row*528 + k*33 + lane]
    const int tid = threadIdx.x, lane = tid & 31, wid = tid >> 5;
    const int pair = wid >> 1, half = wid & 1;
    const int b0 = blockIdx.x * 8 + pair * 2;
    const int hoff = half * 512;
    const float* TW = &g_twTab[0];

    u64 t0[8], t1[8];
    #pragma unroll
    for (int q = 0; q < 4; ++q) {
        const u64* ti = reinterpret_cast<const u64*>(&g_tinit[hoff + (lane + 32 * q) * 4]);
        t0[2*q] = ti[0];  t0[2*q+1] = ti[1];
        t1[2*q] = ti[0];  t1[2*q+1] = ti[1];
    }

    float* P = sP[wid];
    unsigned xw0 = 0, xw1 = 0;

    u64 va[8], vb[8];
    ldg4_(va, V + hoff, lane);   // prime V row 0

    #pragma unroll 1
    for (int blk = 0; blk < 64; ++blk) {
        if ((blk & 1) == 0) {
            xw0 = g_xb[(unsigned)b0 * 32 + (blk >> 1)];
            xw1 = g_xb[(unsigned)(b0 + 1) * 32 + (blk >> 1)];
        }
        const int dbase = blk * 16;
        const int bp0 = (blk & 1) * 16;

        #pragma unroll 1
        for (int kk = 0; kk < 16; kk += 2) {
            step_(dbase + kk,     bp0 + kk,     kk,     va, vb, t0, t1, xw0, xw1, V, TW, hoff, lane, P);
            step_(dbase + kk + 1, bp0 + kk + 1, kk + 1, vb, va, t0, t1, xw0, xw1, V, TW, hoff, lane, P);
        }

        asm volatile("bar.sync %0, 64;" :: "r"(pair + 1));
        if (lane < 16) {
            // each warp reduces its own row (even: row0, odd: row1)
            const int row = half;
            const float* A  = sP[pair * 2]     + row * 528 + lane * 33;
            const float* Bq = sP[pair * 2 + 1] + row * 528 + lane * 33;
            float s = 0.0f;
            #pragma unroll
            for (int j = 0; j < 32; ++j) s += A[j] + Bq[j];
            const int d0 = dbase + lane;
            const float bb = __ldg(&g_B2[d0]);
            out[(unsigned)(b0 + row) * DD + d0] = sigm_(fmaf(s, 0.5f, bb));
        }
        asm volatile("bar.sync %0, 64;" :: "r"(pair + 1));
    }
}

extern "C" void kernel_launch(void* const* d_in, const int* in_sizes, int n_in,
                              void* d_out, int out_size) {
    const float* x = (const float*)d_in[0];   // (B, D)
    const float* V = (const float*)d_in[1];   // (D, H)
    const float* b = (const float*)d_in[2];   // (D,)
    const float* W = (const float*)d_in[3];   // (H, D)
    const float* c = (const float*)d_in[4];   // (H,)
    float* out = (float*)d_out;               // (B, D)

    prep_tw<<<(HH * DD) / 256, 256>>>(W);
    prep_xb<<<(BB * 32 * 32) / 256, 256>>>(x);
    prep_tc<<<HH / 256, 256>>>(c);
    prep_B2<<<(DD * 32) / 256, 256>>>(V, b);
    nade_main<<<BB / 8, 256>>>(V, out);
}

// round 15
// speedup vs baseline: 2.6043x; 1.1274x over previous
#include <cuda_runtime.h>
#include <cuda_bf16.h>

#define DD 1024
#define HH 1024
#define BB 8192

__device__ __align__(16) float g_twTab[DD * HH]; // NEGATED: -tanh(W[h][d]/2)
__device__ unsigned            g_xb[BB * 32];    // packed x bits [b][d/32]
__device__ __align__(16) float g_tinit[HH];      // tanh(c[h]/2)
__device__ __align__(16) float g_B2[DD];         // b[d] + 0.5*rowsum(V[d])

typedef unsigned long long u64;

__device__ __forceinline__ u64 fma2_(u64 a, u64 b, u64 c) {
    u64 d; asm("fma.rn.f32x2 %0, %1, %2, %3;" : "=l"(d) : "l"(a), "l"(b), "l"(c)); return d;
}
__device__ __forceinline__ u64 mul2_(u64 a, u64 b) {
    u64 d; asm("mul.rn.f32x2 %0, %1, %2;" : "=l"(d) : "l"(a), "l"(b)); return d;
}
__device__ __forceinline__ u64 add2_(u64 a, u64 b) {
    u64 d; asm("add.rn.f32x2 %0, %1, %2;" : "=l"(d) : "l"(a), "l"(b)); return d;
}
__device__ __forceinline__ float frcp_(float x) {
    float r; asm("rcp.approx.f32 %0, %1;" : "=f"(r) : "f"(x)); return r;
}
__device__ __forceinline__ float fex2_(float x) {
    float r; asm("ex2.approx.f32 %0, %1;" : "=f"(r) : "f"(x)); return r;
}
__device__ __forceinline__ void unpack2_(u64 u, float& a, float& b) {
    asm("mov.b64 {%0, %1}, %2;" : "=f"(a), "=f"(b) : "l"(u));
}
__device__ __forceinline__ float sigm_(float t) {
    return frcp_(1.0f + fex2_(-1.4426950408889634f * t));
}

#define ONE2  0x3f8000003f800000ULL
#define MONE2 0xbf800000bf800000ULL

// tanh addition law with NEGATED table (twn = -tw):
//   tau' = (tau + tw)/(1 + tau*tw);  zn = -tau*tw = tau*twn
//   1/(1+z) ~ 1 + zn + zn^2 (deg-2; err |z|^3, sign-random). 5 ops, no MUFU.
__device__ __forceinline__ void upd_(u64& tau, u64 twn) {
    u64 zn  = mul2_(tau, twn);
    u64 num = fma2_(twn, MONE2, tau);     // tau + tw
    u64 p   = add2_(ONE2, zn);
    p = fma2_(zn, p, ONE2);
    tau = mul2_(num, p);
}

__device__ __forceinline__ void ldg4_(u64* dst, const float* base, int lane) {
    const ulonglong2* p = reinterpret_cast<const ulonglong2*>(base);
    #pragma unroll
    for (int q = 0; q < 4; ++q) {
        ulonglong2 v = __ldg(&p[lane + 32 * q]);
        dst[2*q] = v.x; dst[2*q+1] = v.y;
    }
}

// -------- fused precompute (2 launches per kernel_launch => ncu hits nade_main) --------
#define NB_TW (DD * HH / 256)        // 16384
#define NB_XB (BB * DD / 256)        // 32768
#define NB_TC 4
#define NB_B2 128

__global__ void prep_all(const float* __restrict__ x, const float* __restrict__ V,
                         const float* __restrict__ bvec, const float* __restrict__ W,
                         const float* __restrict__ c) {
    const int blk = blockIdx.x;
    if (blk < NB_TW) {
        int i = blk * 256 + threadIdx.x;           // over H*D, W row-major [H][D]
        int h = i >> 10, d = i & 1023;
        g_twTab[d * HH + h] = -tanhf(0.5f * W[i]); // negated
    } else if (blk < NB_TW + NB_XB) {
        int gtid = (blk - NB_TW) * 256 + threadIdx.x;
        int warp = gtid >> 5, lane = gtid & 31;
        int b = warp >> 5, ch = warp & 31;
        float v = x[b * DD + ch * 32 + lane];
        unsigned m = __ballot_sync(0xffffffffu, v != 0.0f);
        if (lane == 0) g_xb[b * 32 + ch] = m;
    } else if (blk < NB_TW + NB_XB + NB_TC) {
        int h = (blk - NB_TW - NB_XB) * 256 + threadIdx.x;
        g_tinit[h] = tanhf(0.5f * c[h]);
    } else {
        int warp = ((blk - NB_TW - NB_XB - NB_TC) * 256 + threadIdx.x) >> 5;
        int lane = threadIdx.x & 31;
        float s = 0.0f;
        const float4* row = reinterpret_cast<const float4*>(V + warp * HH);
        #pragma unroll
        for (int q = 0; q < 8; ++q) {
            float4 v = row[lane + 32 * q];
            s += (v.x + v.y) + (v.z + v.w);
        }
        #pragma unroll
        for (int off = 16; off; off >>= 1) s += __shfl_xor_sync(0xffffffffu, s, off);
        if (lane == 0) g_B2[warp] = bvec[warp] + 0.5f * s;
    }
}

// -------- main --------
// Warp PAIR owns 4 batch rows; warp (wid&1) owns h-half [half*512, +512).
// tau state: 4 rows x 8 u64. One V-row load feeds 4 dots; tw-row load amortized.
// Per 8-step block: partials -> padded smem (stride 36/288), pair-scoped bar,
// both warps reduce 2 rows each, coalesced-ish output.
__global__ void __launch_bounds__(256, 2)
nade_main(const float* __restrict__ V, float* __restrict__ out) {
    __shared__ float sP[8 * 1152];    // [warp][row*288 + k*36 + lane]
    const int tid = threadIdx.x, lane = tid & 31, wid = tid >> 5;
    const int pair = wid >> 1, half = wid & 1;
    const int b0 = blockIdx.x * 16 + pair * 4;
    const int hoff = half * 512;
    const float* TWN = &g_twTab[0];

    u64 t[4][8];
    #pragma unroll
    for (int q = 0; q < 4; ++q) {
        const u64* ti = reinterpret_cast<const u64*>(&g_tinit[hoff + (lane + 32 * q) * 4]);
        u64 lo = ti[0], hi = ti[1];
        #pragma unroll
        for (int r = 0; r < 4; ++r) { t[r][2*q] = lo; t[r][2*q+1] = hi; }
    }

    float* P = sP + wid * 1152;
    unsigned xw[4] = {0, 0, 0, 0};

    u64 v[8];
    ldg4_(v, V + hoff, lane);   // prime V row 0

    #pragma unroll 1
    for (int blk = 0; blk < 128; ++blk) {
        if ((blk & 3) == 0) {
            #pragma unroll
            for (int r = 0; r < 4; ++r)
                xw[r] = __ldg(&g_xb[(unsigned)(b0 + r) * 32 + (blk >> 2)]);
        }
        const int dbase = blk * 8;

        #pragma unroll 1
        for (int k = 0; k < 8; ++k) {
            const int d = dbase + k;
            const int bitpos = (blk & 3) * 8 + k;

            // dots: 4 rows share V registers
            u64 a0[4], a1[4];
            #pragma unroll
            for (int r = 0; r < 4; ++r) { a0[r] = 0ULL; a1[r] = 0ULL; }
            #pragma unroll
            for (int q = 0; q < 4; ++q) {
                #pragma unroll
                for (int r = 0; r < 4; ++r) {
                    a0[r] = fma2_(t[r][2*q],   v[2*q],   a0[r]);
                    a1[r] = fma2_(t[r][2*q+1], v[2*q+1], a1[r]);
                }
            }
            #pragma unroll
            for (int r = 0; r < 4; ++r) {
                u64 s2 = add2_(a0[r], a1[r]);
                float xa, xb2; unpack2_(s2, xa, xb2);
                P[r * 288 + k * 36 + lane] = xa + xb2;
            }

            // prefetch next V row (WAR on v; overlaps the update below)
            ldg4_(v, V + (size_t)((d + 1) & (DD - 1)) * HH + hoff, lane);

            // conditional updates (warp-uniform branches)
            const unsigned bit = 1u << bitpos;
            if ((xw[0] | xw[1] | xw[2] | xw[3]) & bit) {
                u64 tw[8];
                ldg4_(tw, TWN + (size_t)d * HH + hoff, lane);
                #pragma unroll
                for (int r = 0; r < 4; ++r) {
                    if (xw[r] & bit) {
                        #pragma unroll
                        for (int q = 0; q < 8; ++q) upd_(t[r][q], tw[q]);
                    }
                }
            }
        }

        asm volatile("bar.sync %0, 64;" :: "r"(pair + 1) : "memory");
        if (lane < 16) {
            const int row2 = half * 2 + (lane >> 3);   // this warp's 2 rows
            const int step = lane & 7;
            const float* A0 = sP + (pair * 2)     * 1152 + row2 * 288 + step * 36;
            const float* A1 = sP + (pair * 2 + 1) * 1152 + row2 * 288 + step * 36;
            float s = 0.0f;
            #pragma unroll
            for (int j = 0; j < 32; j += 4) {
                float4 u0 = *reinterpret_cast<const float4*>(A0 + j);
                float4 u1 = *reinterpret_cast<const float4*>(A1 + j);
                s += ((u0.x + u0.y) + (u0.z + u0.w)) + ((u1.x + u1.y) + (u1.z + u1.w));
            }
            const int d0 = dbase + step;
            out[(unsigned)(b0 + row2) * DD + d0] = sigm_(fmaf(s, 0.5f, __ldg(&g_B2[d0])));
        }
        asm volatile("bar.sync %0, 64;" :: "r"(pair + 1) : "memory");
    }
}

extern "C" void kernel_launch(void* const* d_in, const int* in_sizes, int n_in,
                              void* d_out, int out_size) {
    const float* x = (const float*)d_in[0];   // (B, D)
    const float* V = (const float*)d_in[1];   // (D, H)
    const float* b = (const float*)d_in[2];   // (D,)
    const float* W = (const float*)d_in[3];   // (H, D)
    const float* c = (const float*)d_in[4];   // (H,)
    float* out = (float*)d_out;               // (B, D)

    prep_all<<<NB_TW + NB_XB + NB_TC + NB_B2, 256>>>(x, V, b, W, c);
    nade_main<<<BB / 16, 256>>>(V, out);
}

// round 16
// speedup vs baseline: 2.7367x; 1.0508x over previous
#include <cuda_runtime.h>
#include <cuda_bf16.h>

#define DD 1024
#define HH 1024
#define BB 8192

__device__ __align__(16) float g_twTab[DD * HH]; // NEGATED: -tanh(W[h][d]/2)
__device__ unsigned            g_xb[BB * 32];    // packed x bits [b][d/32]
__device__ __align__(16) float g_tinit[HH];      // tanh(c[h]/2)
__device__ __align__(16) float g_B2[DD];         // b[d] + 0.5*rowsum(V[d])

typedef unsigned long long u64;

__device__ __forceinline__ u64 fma2_(u64 a, u64 b, u64 c) {
    u64 d; asm("fma.rn.f32x2 %0, %1, %2, %3;" : "=l"(d) : "l"(a), "l"(b), "l"(c)); return d;
}
__device__ __forceinline__ u64 mul2_(u64 a, u64 b) {
    u64 d; asm("mul.rn.f32x2 %0, %1, %2;" : "=l"(d) : "l"(a), "l"(b)); return d;
}
__device__ __forceinline__ u64 add2_(u64 a, u64 b) {
    u64 d; asm("add.rn.f32x2 %0, %1, %2;" : "=l"(d) : "l"(a), "l"(b)); return d;
}
__device__ __forceinline__ float frcp_(float x) {
    float r; asm("rcp.approx.f32 %0, %1;" : "=f"(r) : "f"(x)); return r;
}
__device__ __forceinline__ float fex2_(float x) {
    float r; asm("ex2.approx.f32 %0, %1;" : "=f"(r) : "f"(x)); return r;
}
__device__ __forceinline__ void unpack2_(u64 u, float& a, float& b) {
    asm("mov.b64 {%0, %1}, %2;" : "=f"(a), "=f"(b) : "l"(u));
}
__device__ __forceinline__ float sigm_(float t) {
    return frcp_(1.0f + fex2_(-1.4426950408889634f * t));
}

#define ONE2  0x3f8000003f800000ULL
#define MONE2 0xbf800000bf800000ULL

// tanh addition law with NEGATED table (twn = -tw):
//   tau' = (tau + tw)/(1 + tau*tw);  zn = -tau*tw = tau*twn
//   1/(1+z) ~ 1 + zn + zn^2 (deg-2; err +z^3 is sign-random). 5 ops, no MUFU.
__device__ __forceinline__ void upd_(u64& tau, u64 twn) {
    u64 zn  = mul2_(tau, twn);
    u64 num = fma2_(twn, MONE2, tau);     // tau + tw
    u64 p   = add2_(ONE2, zn);
    p = fma2_(zn, p, ONE2);
    tau = mul2_(num, p);
}

__device__ __forceinline__ void ldg4_(u64* dst, const float* base, int lane) {
    const ulonglong2* p = reinterpret_cast<const ulonglong2*>(base);
    #pragma unroll
    for (int q = 0; q < 4; ++q) {
        ulonglong2 v = __ldg(&p[lane + 32 * q]);
        dst[2*q] = v.x; dst[2*q+1] = v.y;
    }
}

// -------- fused precompute --------
#define NB_TW (DD * HH / 256)        // 16384
#define NB_XB (BB * DD / 256)        // 32768
#define NB_TC 4
#define NB_B2 128

__global__ void prep_all(const float* __restrict__ x, const float* __restrict__ V,
                         const float* __restrict__ bvec, const float* __restrict__ W,
                         const float* __restrict__ c) {
    const int blk = blockIdx.x;
    if (blk < NB_TW) {
        int i = blk * 256 + threadIdx.x;           // over H*D, W row-major [H][D]
        int h = i >> 10, d = i & 1023;
        g_twTab[d * HH + h] = -tanhf(0.5f * W[i]); // negated
    } else if (blk < NB_TW + NB_XB) {
        int gtid = (blk - NB_TW) * 256 + threadIdx.x;
        int warp = gtid >> 5, lane = gtid & 31;
        int b = warp >> 5, ch = warp & 31;
        float v = x[b * DD + ch * 32 + lane];
        unsigned m = __ballot_sync(0xffffffffu, v != 0.0f);
        if (lane == 0) g_xb[b * 32 + ch] = m;
    } else if (blk < NB_TW + NB_XB + NB_TC) {
        int h = (blk - NB_TW - NB_XB) * 256 + threadIdx.x;
        g_tinit[h] = tanhf(0.5f * c[h]);
    } else {
        int warp = ((blk - NB_TW - NB_XB - NB_TC) * 256 + threadIdx.x) >> 5;
        int lane = threadIdx.x & 31;
        float s = 0.0f;
        const float4* row = reinterpret_cast<const float4*>(V + warp * HH);
        #pragma unroll
        for (int q = 0; q < 8; ++q) {
            float4 v = row[lane + 32 * q];
            s += (v.x + v.y) + (v.z + v.w);
        }
        #pragma unroll
        for (int off = 16; off; off >>= 1) s += __shfl_xor_sync(0xffffffffu, s, off);
        if (lane == 0) g_B2[warp] = bvec[warp] + 0.5f * s;
    }
}

// -------- main --------
// Warp PAIR owns 4 batch rows; warp (wid&1) owns h-half [half*512, +512).
// tau state: 4 rows x 8 u64. One V-row load feeds 4 dots; tw-row load amortized.
// tw load hoisted ABOVE the dot so its latency overlaps independent dot work.
__global__ void __launch_bounds__(256, 2)
nade_main(const float* __restrict__ V, float* __restrict__ out) {
    __shared__ float sP[8 * 1152];    // [warp][row*288 + k*36 + lane]
    const int tid = threadIdx.x, lane = tid & 31, wid = tid >> 5;
    const int pair = wid >> 1, half = wid & 1;
    const int b0 = blockIdx.x * 16 + pair * 4;
    const int hoff = half * 512;
    const float* TWN = &g_twTab[0];

    u64 t[4][8];
    #pragma unroll
    for (int q = 0; q < 4; ++q) {
        const u64* ti = reinterpret_cast<const u64*>(&g_tinit[hoff + (lane + 32 * q) * 4]);
        u64 lo = ti[0], hi = ti[1];
        #pragma unroll
        for (int r = 0; r < 4; ++r) { t[r][2*q] = lo; t[r][2*q+1] = hi; }
    }

    float* P = sP + wid * 1152;
    unsigned xw[4] = {0, 0, 0, 0};

    u64 v[8];
    ldg4_(v, V + hoff, lane);   // prime V row 0

    #pragma unroll 1
    for (int blk = 0; blk < 128; ++blk) {
        if ((blk & 3) == 0) {
            #pragma unroll
            for (int r = 0; r < 4; ++r)
                xw[r] = __ldg(&g_xb[(unsigned)(b0 + r) * 32 + (blk >> 2)]);
        }
        const int dbase = blk * 8;

        #pragma unroll 2
        for (int k = 0; k < 8; ++k) {
            const int d = dbase + k;
            const int bitpos = (blk & 3) * 8 + k;
            const unsigned bit = 1u << bitpos;
            const bool anyupd = ((xw[0] | xw[1] | xw[2] | xw[3]) & bit) != 0u;

            // tw load FIRST: latency overlaps the independent dot below
            u64 tw[8];
            if (anyupd) ldg4_(tw, TWN + (size_t)d * HH + hoff, lane);

            // dots: 4 rows share V registers
            u64 a0[4], a1[4];
            #pragma unroll
            for (int r = 0; r < 4; ++r) { a0[r] = 0ULL; a1[r] = 0ULL; }
            #pragma unroll
            for (int q = 0; q < 4; ++q) {
                #pragma unroll
                for (int r = 0; r < 4; ++r) {
                    a0[r] = fma2_(t[r][2*q],   v[2*q],   a0[r]);
                    a1[r] = fma2_(t[r][2*q+1], v[2*q+1], a1[r]);
                }
            }
            #pragma unroll
            for (int r = 0; r < 4; ++r) {
                u64 s2 = add2_(a0[r], a1[r]);
                float xa, xb2; unpack2_(s2, xa, xb2);
                P[r * 288 + k * 36 + lane] = xa + xb2;
            }

            // prefetch next V row (WAR on v; overlaps the update below)
            ldg4_(v, V + (size_t)((d + 1) & (DD - 1)) * HH + hoff, lane);

            // conditional updates (warp-uniform branches)
            if (anyupd) {
                #pragma unroll
                for (int r = 0; r < 4; ++r) {
                    if (xw[r] & bit) {
                        #pragma unroll
                        for (int q = 0; q < 8; ++q) upd_(t[r][q], tw[q]);
                    }
                }
            }
        }

        asm volatile("bar.sync %0, 64;" :: "r"(pair + 1) : "memory");
        if (lane < 16) {
            const int row2 = half * 2 + (lane >> 3);   // this warp's 2 rows
            const int step = lane & 7;
            const float* A0 = sP + (pair * 2)     * 1152 + row2 * 288 + step * 36;
            const float* A1 = sP + (pair * 2 + 1) * 1152 + row2 * 288 + step * 36;
            float s = 0.0f;
            #pragma unroll
            for (int j = 0; j < 32; j += 4) {
                float4 u0 = *reinterpret_cast<const float4*>(A0 + j);
                float4 u1 = *reinterpret_cast<const float4*>(A1 + j);
                s += ((u0.x + u0.y) + (u0.z + u0.w)) + ((u1.x + u1.y) + (u1.z + u1.w));
            }
            const int d0 = dbase + step;
            out[(unsigned)(b0 + row2) * DD + d0] = sigm_(fmaf(s, 0.5f, __ldg(&g_B2[d0])));
        }
        asm volatile("bar.sync %0, 64;" :: "r"(pair + 1) : "memory");
    }
}

extern "C" void kernel_launch(void* const* d_in, const int* in_sizes, int n_in,
                              void* d_out, int out_size) {
    const float* x = (const float*)d_in[0];   // (B, D)
    const float* V = (const float*)d_in[1];   // (D, H)
    const float* b = (const float*)d_in[2];   // (D,)
    const float* W = (const float*)d_in[3];   // (H, D)
    const float* c = (const float*)d_in[4];   // (H,)
    float* out = (float*)d_out;               // (B, D)

    prep_all<<<NB_TW + NB_XB + NB_TC + NB_B2, 256>>>(x, V, b, W, c);
    nade_main<<<BB / 16, 256>>>(V, out);
}